// round 11
// baseline (speedup 1.0000x reference)
#include <cuda_runtime.h>

#define F  16
#define C  16
#define NB 100
#define NE 101
#define NS 102          // sbin+1 range: 0..101
#define MAXN 100000
#define GRID1 148       // k_minmax grid (fixed; ticket pattern assumes this)
#define BS1   1024

// ---------------- device scratch (static, no allocations) ----------------
__device__ float    g_part_lo[GRID1][F];
__device__ float    g_part_hi[GRID1][F];
__device__ int      g_ticket;                 // zero at load; last block resets to 0 each run
__device__ float    g_edges[F * NE];
__device__ float    g_lo[F];
__device__ float    g_scale[F];
__device__ int      g_counts[F * NB];
__device__ int      g_cbin[C * F];            // [c][f], raw bins (-1..100)
__device__ unsigned char g_sbin[MAXN * F];    // sbin+1 (0..101)

// searchsorted over e[0..NE-1]:
//   rR = #{j : e[j] <= v}  (side='right'),  rL = #{j : e[j] < v}  (side='left')
__device__ __forceinline__ void search2(const float* e, float v,
                                        float lo, float scale, int& rR, int& rL) {
    int g = (int)((v - lo) * scale);
    g = min(max(g, 0), NE);
    while (g < NE && e[g] <= v) ++g;
    while (g > 0 && e[g - 1] > v) --g;
    rR = g;
    while (g > 0 && e[g - 1] >= v) --g;
    rL = g;
}

__device__ __forceinline__ float4 ld_comb(const float* __restrict__ z,
                                          const float* __restrict__ cl,
                                          int i, int zf4) {
    return (i < zf4) ? ((const float4*)z)[i] : ((const float4*)cl)[i - zf4];
}
__device__ __forceinline__ void acc4(float4& mn4, float4& mx4, float4 v) {
    mn4.x = fminf(mn4.x, v.x); mx4.x = fmaxf(mx4.x, v.x);
    mn4.y = fminf(mn4.y, v.y); mx4.y = fmaxf(mx4.y, v.y);
    mn4.z = fminf(mn4.z, v.z); mx4.z = fmaxf(mx4.z, v.z);
    mn4.w = fminf(mn4.w, v.w); mx4.w = fmaxf(mx4.w, v.w);
}

// =================== K1: minmax (clamped 3-load, MLP=3) + parallel tail ===================
__global__ void __launch_bounds__(BS1) k_minmax(const float* __restrict__ z,
                                                const float* __restrict__ cl, int N) {
    int t = threadIdx.x, b = blockIdx.x;
    if (b == 0)
        for (int i = t; i < F * NB; i += BS1) g_counts[i] = 0;

    const float INF = __int_as_float(0x7f800000);
    float4 mn4 = make_float4(INF, INF, INF, INF);
    float4 mx4 = make_float4(-INF, -INF, -INF, -INF);

    // flat float4 stream. 3 clamped loads per thread cover total4 (<= 3*GRID1*BS1).
    // Clamping keeps (i & 3) group only for in-range indices; the clamp target is
    // total4-1 whose group may differ -- but duplicated values only tighten nothing:
    // min/max over extra *valid stream values of the wrong feature group* would be
    // WRONG. So clamp per-load to the last index with the SAME group instead.
    int total4 = (N + C) * 4;
    int zf4    = N * 4;
    const int S = GRID1 * BS1;          // multiple of 4 -> group preserved by strides
    int grp = t & 3;
    // last flat index of this group: total4-4+grp (total4 is a multiple of 4)
    int last_same_grp = total4 - 4 + grp;
    int i0 = b * BS1 + t;
    int i1 = min(i0 + S,     last_same_grp);
    int i2 = min(i0 + 2 * S, last_same_grp);
    i0 = min(i0, last_same_grp);
    float4 v0 = ld_comb(z, cl, i0, zf4);
    float4 v1 = ld_comb(z, cl, i1, zf4);
    float4 v2 = ld_comb(z, cl, i2, zf4);
    acc4(mn4, mx4, v0); acc4(mn4, mx4, v1); acc4(mn4, mx4, v2);

    // combine lanes with the same group (lane & 3)
#pragma unroll
    for (int o = 4; o < 32; o <<= 1) {
        mn4.x = fminf(mn4.x, __shfl_xor_sync(0xffffffffu, mn4.x, o));
        mn4.y = fminf(mn4.y, __shfl_xor_sync(0xffffffffu, mn4.y, o));
        mn4.z = fminf(mn4.z, __shfl_xor_sync(0xffffffffu, mn4.z, o));
        mn4.w = fminf(mn4.w, __shfl_xor_sync(0xffffffffu, mn4.w, o));
        mx4.x = fmaxf(mx4.x, __shfl_xor_sync(0xffffffffu, mx4.x, o));
        mx4.y = fmaxf(mx4.y, __shfl_xor_sync(0xffffffffu, mx4.y, o));
        mx4.z = fmaxf(mx4.z, __shfl_xor_sync(0xffffffffu, mx4.z, o));
        mx4.w = fmaxf(mx4.w, __shfl_xor_sync(0xffffffffu, mx4.w, o));
    }
    __shared__ float swlo[BS1 / 32][F], swhi[BS1 / 32][F];
    int w = t >> 5, lane = t & 31;
    if (lane < 4) {          // lane g holds features 4g..4g+3
        swlo[w][4 * lane + 0] = mn4.x; swhi[w][4 * lane + 0] = mx4.x;
        swlo[w][4 * lane + 1] = mn4.y; swhi[w][4 * lane + 1] = mx4.y;
        swlo[w][4 * lane + 2] = mn4.z; swhi[w][4 * lane + 2] = mx4.z;
        swlo[w][4 * lane + 3] = mn4.w; swhi[w][4 * lane + 3] = mx4.w;
    }
    __syncthreads();
    if (t < F) {
        float lo = swlo[0][t], hi = swhi[0][t];
#pragma unroll
        for (int ww = 1; ww < BS1 / 32; ww++) {
            lo = fminf(lo, swlo[ww][t]); hi = fmaxf(hi, swhi[ww][t]);
        }
        g_part_lo[b][t] = lo;
        g_part_hi[b][t] = hi;
    }
    __threadfence();          // publish partials (and block-0 zeroing)
    __syncthreads();
    __shared__ int sLast;
    if (t == 0) sLast = (atomicAdd(&g_ticket, 1) == GRID1 - 1);
    __syncthreads();
    if (!sLast) return;
    __threadfence();          // acquire side

    // ---- last block: fully parallel partial reduce, all in shared ----
    __shared__ float s_rlo[F * GRID1], s_rhi[F * GRID1];
    for (int j = t; j < F * GRID1; j += BS1) {
        int b2 = j >> 4, f = j & 15;
        s_rlo[f * GRID1 + b2] = __ldcg(&g_part_lo[b2][f]);
        s_rhi[f * GRID1 + b2] = __ldcg(&g_part_hi[b2][f]);
    }
    __syncthreads();
    __shared__ float flo[F], fhi[F], fsc[F];
    if (w < 2 * F) {          // warp w<16: min of feature w; warp 16+f: max of feature f
        bool isHi = (w >= F);
        int f = isHi ? (w - F) : w;
        const float* src = isHi ? s_rhi : s_rlo;
        float v = isHi ? -INF : INF;
        for (int k = lane; k < GRID1; k += 32)
            v = isHi ? fmaxf(v, src[f * GRID1 + k]) : fminf(v, src[f * GRID1 + k]);
#pragma unroll
        for (int o = 16; o > 0; o >>= 1) {
            float u = __shfl_xor_sync(0xffffffffu, v, o);
            v = isHi ? fmaxf(v, u) : fminf(v, u);
        }
        if (lane == 0) { if (isHi) fhi[f] = v; else flo[f] = v; }
    }
    __syncthreads();
    if (t < F) {
        float lo = flo[t], hi = fhi[t];
        fsc[t] = (hi > lo) ? (float)NB / (hi - lo) : 0.0f;
        g_lo[t] = lo; g_scale[t] = fsc[t];
    }
    __syncthreads();
    // edges[f][j] = lo + (hi-lo)*t_j, t_j = j*0.01f in f32 (no fma contraction)
    __shared__ float s_edges[F * NE];          // shared copy for the tail search
    for (int i2e = t; i2e < F * NE; i2e += BS1) {
        int f = i2e / NE, j = i2e % NE;
        float tt = (j == NB) ? 1.0f : __fmul_rn((float)j, 0.01f);
        float e = __fadd_rn(flo[f], __fmul_rn(__fsub_rn(fhi[f], flo[f]), tt));
        s_edges[i2e] = e;
        g_edges[i2e] = e;
    }
    __syncthreads();
    if (t < C * F) {                           // search against SHARED edges (29cyc steps)
        int c = t / F, f = t % F;
        int rR, rL;
        search2(&s_edges[f * NE], cl[c * F + f], flo[f], fsc[f], rR, rL);
        atomicAdd(&g_counts[f * NB + min(max(rR - 1, 0), NB - 1)], 1);
        g_cbin[t] = rL - 1;               // t == c*F + f
    }
    __threadfence();
    if (t == 0) g_ticket = 0;             // reset for next graph replay
}

// =================== K2: bin z (match-dedup per-warp u8 hist, no ATOMS) ===================
__global__ void __launch_bounds__(256) k_bin(const float* __restrict__ z, int N) {
    __shared__ float se[F * NE];
    __shared__ float slo[F], ssc[F];
    __shared__ unsigned char h8[8][F * NB];   // per-warp hist, counts <= 32 fit u8
    int t = threadIdx.x;
    for (int i = t; i < F * NE; i += 256) se[i] = g_edges[i];
    if (t < F) { slo[t] = g_lo[t]; ssc[t] = g_scale[t]; }
    for (int i = t; i < (8 * F * NB) / 4; i += 256) ((unsigned*)h8)[i] = 0u;
    __syncthreads();

    int n = blockIdx.x * 256 + t;                // one row per lane (grid covers N)
    bool valid = (n < N);
    int w = t >> 5, lane = t & 31;
    float v[F];
    if (valid) {
        const float4* zp = (const float4*)(z + (size_t)n * F);
#pragma unroll
        for (int j = 0; j < 4; j++) {
            float4 x = zp[j];
            v[4*j+0] = x.x; v[4*j+1] = x.y; v[4*j+2] = x.z; v[4*j+3] = x.w;
        }
    }
    unsigned pk[4] = {0, 0, 0, 0};
#pragma unroll
    for (int f = 0; f < F; f++) {
        int key = 127, rL = 0;
        if (valid) {
            int rR;
            search2(&se[f * NE], v[f], slo[f], ssc[f], rR, rL);
            key = min(max(rR - 1, 0), NB - 1);
        }
        unsigned mask = __match_any_sync(0xffffffffu, key);
        if (valid && lane == (__ffs(mask) - 1)) {
            int idx = f * NB + key;
            h8[w][idx] = (unsigned char)(h8[w][idx] + __popc(mask));
        }
        pk[f >> 2] |= (unsigned)rL << (8 * (f & 3));
    }
    if (valid) {
        uint4 o; o.x = pk[0]; o.y = pk[1]; o.z = pk[2]; o.w = pk[3];
        *(uint4*)(g_sbin + (size_t)n * F) = o;
    }
    __syncthreads();
    // merge 8 warp copies -> global (byte-extract, 4 bins per u32 word)
    for (int wi = t; wi < (F * NB) / 4; wi += 256) {
        unsigned s0 = 0, s1 = 0, s2 = 0, s3 = 0;
#pragma unroll
        for (int ww = 0; ww < 8; ww++) {
            unsigned x = ((const unsigned*)h8[ww])[wi];
            s0 += x & 255u; s1 += (x >> 8) & 255u; s2 += (x >> 16) & 255u; s3 += (x >> 24);
        }
        int b = wi * 4;
        if (s0) atomicAdd(&g_counts[b + 0], (int)s0);
        if (s1) atomicAdd(&g_counts[b + 1], (int)s1);
        if (s2) atomicAdd(&g_counts[b + 2], (int)s2);
        if (s3) atomicAdd(&g_counts[b + 3], (int)s3);
    }
}

// =================== K3: cum + G build (per block) + main reduction ===================
__global__ void __launch_bounds__(1024) k_main(float* __restrict__ out, int N, float inv_div) {
    extern __shared__ float sG[];             // F*NS*C floats (104448 B)
    __shared__ float scum[F * NB];
    __shared__ int   scbin[C * F];
    int t = threadIdx.x;
    const int bs = 1024;

    int* stage = (int*)sG;                    // reuse sG front as count staging
    for (int i = t; i < F * NB; i += bs) stage[i] = g_counts[i];
    if (t < C * F) scbin[t] = g_cbin[t];
    __syncthreads();
    int w = t >> 5, lane = t & 31;
    if (w < F) {                              // warp-per-feature inclusive scan
        float carry = 0.0f;                   // integer-valued -> exact in f32
#pragma unroll
        for (int ch = 0; ch < 4; ch++) {
            int idx = ch * 32 + lane;
            float v = (idx < NB) ? (float)stage[w * NB + idx] : 0.0f;
#pragma unroll
            for (int o = 1; o < 32; o <<= 1) {
                float u = __shfl_up_sync(0xffffffffu, v, o);
                if (lane >= o) v += u;
            }
            v += carry;
            if (idx < NB) scum[w * NB + idx] = v;
            carry = __shfl_sync(0xffffffffu, v, 31);
        }
    }
    __syncthreads();
    for (int i = t; i < F * NS * C; i += bs) {
        int c = i & (C - 1);
        int s = (i >> 4) % NS;                // const-div -> mul/shift
        int f = i / (NS * C);
        int sb = s - 1, cb = scbin[c * F + f];
        int mxb = max(sb, cb), mnb = min(sb, cb);
        float hiS = scum[f * NB + min(max(mxb, 0), NB - 1)];
        float val = (mnb <= 0) ? hiS : (hiS - scum[f * NB + (mnb - 1)]);  // exact ints
        float ratio = __fmul_rn(val, inv_div);
        sG[i] = __fmul_rn(ratio, ratio);
    }
    __syncthreads();

    int npairs = N * C;
    int stride = gridDim.x * bs;
    for (int p0 = blockIdx.x * bs; p0 < npairs; p0 += stride) {
        int p = p0 + t;
        bool act = (p < npairs);
        int c = p & (C - 1);
        int n = min(p >> 4, N - 1);
        uint4 wv = *(const uint4*)(g_sbin + (size_t)n * F);
        unsigned ww[4] = {wv.x, wv.y, wv.z, wv.w};
        float acc = 0.0f;
#pragma unroll
        for (int f = 0; f < F; f++) {
            unsigned s = (ww[f >> 2] >> (8 * (f & 3))) & 0xFFu;
            acc += sG[(f * NS + (int)s) * C + c];
        }
        float a2 = fmaxf(acc, 1e-30f);
        float m  = a2 * rsqrtf(a2);               // fast sqrt (MUFU.RSQ)
        float qv = __fdividef(1.0f, 1.0f + m);    // fast div
        float ssum = qv;
#pragma unroll
        for (int o = 1; o < 16; o <<= 1)
            ssum += __shfl_xor_sync(0xffffffffu, ssum, o);
        if (act) out[p] = __fdividef(qv, ssum);
    }
}

// ---------------- launch ----------------
extern "C" void kernel_launch(void* const* d_in, const int* in_sizes, int n_in,
                              void* d_out, int out_size) {
    const float* z  = (const float*)d_in[0];
    const float* cl = (const float*)d_in[1];
    float* out = (float*)d_out;
    int N = in_sizes[0] / F;
    float inv_div = 1.0f / (float)(N + C);

    cudaFuncSetAttribute(k_main, cudaFuncAttributeMaxDynamicSharedMemorySize,
                         F * NS * C * (int)sizeof(float));

    k_minmax<<<GRID1, BS1>>>(z, cl, N);
    k_bin<<<(N + 255) / 256, 256>>>(z, N);
    k_main<<<148, 1024, F * NS * C * (int)sizeof(float)>>>(out, N, inv_div);
}